// round 13
// baseline (speedup 1.0000x reference)
#include <cuda_runtime.h>
#include <math.h>

// Problem constants: T=70, B=64, V=10000, E=512, H=1024, L=2
#define T_  70
#define B_  64
#define V_  10000
#define E_  512
#define H_  1024
#define MTOT (T_ * B_)          // 4480 = 35 * 128
#define BH   (B_ * H_)          // 65536

// Scratch (__device__ globals: allocation-free rule)
__device__ float    g_X0[(size_t)MTOT * H_];
__device__ float    g_P[(size_t)16 * BH];       // partials: [0..8)=y0, [8..16)=y1
__device__ unsigned g_Htf0[(size_t)T_ * BH];    // tf32 h0_t, k-pair interleaved
__device__ unsigned g_Htf1[(size_t)T_ * BH];    // tf32 h1_t, k-pair interleaved
__device__ unsigned g_H1lin[(size_t)MTOT * H_]; // tf32 linear h1 (logits A-side)
__device__ float    g_Hfin0[BH];                // fp32 h0[T-1]
__device__ float    g_Hfin1[BH];                // fp32 h1[T-1]
__device__ unsigned g_flags[128];               // per-block barrier flags

// tf32 pre-converted GEMM operands
__device__ unsigned g_emb_tf[(size_t)V_ * E_];
__device__ unsigned g_Wx0tf[(size_t)H_ * E_];
__device__ unsigned g_Wytf [(size_t)V_ * H_];

__global__ void bar_init() { g_flags[threadIdx.x] = 0u; }

__device__ __forceinline__ unsigned f2tf(float x) {
    unsigned r; asm("cvt.rna.tf32.f32 %0, %1;" : "=r"(r) : "f"(x)); return r;
}

// fp32 -> tf32(rna) bulk convert (n4 = n/4 float4s)
__global__ void cvt_tf32(const float* __restrict__ s, unsigned* __restrict__ d, int n4) {
    const int i = blockIdx.x * 256 + threadIdx.x;
    if (i < n4) {
        const float4 v = ((const float4*)s)[i];
        ((uint4*)d)[i] = make_uint4(f2tf(v.x), f2tf(v.y), f2tf(v.z), f2tf(v.w));
    }
}

// Contention-free grid barrier (128 co-resident blocks, 1/SM).
__device__ __forceinline__ void gridbar(int bid, unsigned phase) {
    __threadfence();
    __syncthreads();
    if (threadIdx.x == 0)
        atomicExch(&g_flags[bid], phase);
    if (threadIdx.x < 128) {
        volatile unsigned* vf = g_flags;
        while (vf[threadIdx.x] < phase) __nanosleep(32);
    }
    __syncthreads();
    __threadfence();
}

__device__ __forceinline__ void mma_tf32(float c[4], const unsigned a[4], const unsigned b[2]) {
    asm volatile(
        "mma.sync.aligned.m16n8k8.row.col.f32.tf32.tf32.f32 "
        "{%0,%1,%2,%3}, {%4,%5,%6,%7}, {%8,%9}, {%0,%1,%2,%3};\n"
        : "+f"(c[0]), "+f"(c[1]), "+f"(c[2]), "+f"(c[3])
        : "r"(a[0]), "r"(a[1]), "r"(a[2]), "r"(a[3]), "r"(b[0]), "r"(b[1]));
}

// ---------------------------------------------------------------------------
// FUSED two-layer persistent recurrence — unchanged from R12 (measured WIN).
// ---------------------------------------------------------------------------
#define WRD_WH0HI 0
#define WRD_WH0LO 8448
#define WRD_WH1HI 16896
#define WRD_WH1LO 25344
#define WRD_WX1   33792
#define WRD_PB0   42240
#define WRD_PB1   46848
#define RNN2_SMEM (51456 * 4)          // 205824 B

__global__ __launch_bounds__(256) void rnn_fused(
    const float* __restrict__ X0,
    const float* __restrict__ h0init, const float* __restrict__ h1init,
    const float* __restrict__ Wh0, const float* __restrict__ Wx1,
    const float* __restrict__ Wh1, const float* __restrict__ bh1,
    unsigned* __restrict__ H1lin)
{
    extern __shared__ unsigned sw[];
    float* Pb0 = (float*)(sw + WRD_PB0);   // [64][72]
    float* Pb1 = (float*)(sw + WRD_PB1);   // [64][72]

    const int tid = threadIdx.x;
    const int bid = blockIdx.x;
    const int ntile = bid >> 3;
    const int ks    = bid & 7;
    const int n0    = ntile * 64;
    const int kb    = ks * 128;

    // Load W slices once (resident all intervals)
    {
        const int r  = tid >> 2;
        const int q4 = (tid & 3) * 4;
        #pragma unroll
        for (int s = 0; s < 8; s++) {
            const int c  = q4 + s * 16;
            const size_t gi = (size_t)(n0 + r) * H_ + kb + c;
            const int wo = r * 132 + c;
            {
                const float4 w = *(const float4*)&Wh0[gi];
                unsigned a0 = f2tf(w.x), a1 = f2tf(w.y), a2 = f2tf(w.z), a3 = f2tf(w.w);
                unsigned* ph = &sw[WRD_WH0HI + wo];
                unsigned* pl = &sw[WRD_WH0LO + wo];
                ph[0] = a0; ph[1] = a1; ph[2] = a2; ph[3] = a3;
                pl[0] = f2tf(w.x - __uint_as_float(a0));
                pl[1] = f2tf(w.y - __uint_as_float(a1));
                pl[2] = f2tf(w.z - __uint_as_float(a2));
                pl[3] = f2tf(w.w - __uint_as_float(a3));
            }
            {
                const float4 w = *(const float4*)&Wh1[gi];
                unsigned a0 = f2tf(w.x), a1 = f2tf(w.y), a2 = f2tf(w.z), a3 = f2tf(w.w);
                unsigned* ph = &sw[WRD_WH1HI + wo];
                unsigned* pl = &sw[WRD_WH1LO + wo];
                ph[0] = a0; ph[1] = a1; ph[2] = a2; ph[3] = a3;
                pl[0] = f2tf(w.x - __uint_as_float(a0));
                pl[1] = f2tf(w.y - __uint_as_float(a1));
                pl[2] = f2tf(w.z - __uint_as_float(a2));
                pl[3] = f2tf(w.w - __uint_as_float(a3));
            }
            {
                const float4 w = *(const float4*)&Wx1[gi];
                unsigned* p = &sw[WRD_WX1 + wo];
                p[0] = f2tf(w.x); p[1] = f2tf(w.y);
                p[2] = f2tf(w.z); p[3] = f2tf(w.w);
            }
        }
    }
    __syncthreads();

    const int wid  = tid >> 5, lane = tid & 31;
    const int wk   = wid & 1;           // k-half (64 k)
    const int wn   = wid >> 1;          // 0..3 (16-n strip)
    const int gid  = lane >> 2, tig = lane & 3;
    const int kwb  = kb + wk * 64;
    const int klb  = wk * 64;

    float* Pp0 = g_P + (size_t)ks * BH;
    float* Pp1 = g_P + (size_t)(8 + ks) * BH;

    const int e  = bid * 512 + tid * 2;
    const int rm = e >> 10;
    const int rn = e & 1023;
    const int b8 = rn & ~7;
    const int o0 = rn & 7;
    const int tp0 = b8 + ((o0 & 3) * 2) + (o0 >> 2);
    const int tp1 = b8 + (((o0 + 1) & 3) * 2) + ((o0 + 1) >> 2);
    const float b1v0 = bh1[rn], b1v1 = bh1[rn + 1];

    unsigned phase = 0;

    #pragma unroll 1
    for (int t = 0; t <= T_; t++) {
        const bool do0 = (t < T_);
        const bool do1 = (t >= 1);

        float acc0[4][2][4], acc1[4][2][4];
        #pragma unroll
        for (int im = 0; im < 4; im++)
            #pragma unroll
            for (int j = 0; j < 2; j++)
                #pragma unroll
                for (int q = 0; q < 4; q++) { acc0[im][j][q] = 0.f; acc1[im][j][q] = 0.f; }

        const unsigned* Hp0 = g_Htf0 + (size_t)(t - 1) * BH;
        const unsigned* Hp1 = g_Htf1 + (size_t)(t - 2) * BH;

        #pragma unroll 2
        for (int kk = 0; kk < 8; kk++) {
            const int kcol = kwb + kk * 8;

            unsigned af0[4][4];
            if (t == 0) {
                #pragma unroll
                for (int im = 0; im < 4; im++) {
                    const int r0 = im * 16 + gid;
                    af0[im][0] = f2tf(h0init[(size_t)r0 * H_ + kcol + tig]);
                    af0[im][1] = f2tf(h0init[(size_t)(r0 + 8) * H_ + kcol + tig]);
                    af0[im][2] = f2tf(h0init[(size_t)r0 * H_ + kcol + tig + 4]);
                    af0[im][3] = f2tf(h0init[(size_t)(r0 + 8) * H_ + kcol + tig + 4]);
                }
            } else {
                #pragma unroll
                for (int im = 0; im < 4; im++) {
                    const int r0 = im * 16 + gid;
                    const uint2 p0 = *(const uint2*)&Hp0[(size_t)r0 * H_ + kcol + tig * 2];
                    const uint2 p1 = *(const uint2*)&Hp0[(size_t)(r0 + 8) * H_ + kcol + tig * 2];
                    af0[im][0] = p0.x; af0[im][1] = p1.x;
                    af0[im][2] = p0.y; af0[im][3] = p1.y;
                }
            }
            #pragma unroll
            for (int j = 0; j < 2; j++) {
                const int wrow = (wn * 16 + j * 8 + gid) * 132 + klb + kk * 8;
                if (do0) {
                    unsigned bh_[2] = { sw[WRD_WH0HI + wrow + tig], sw[WRD_WH0HI + wrow + tig + 4] };
                    unsigned bl_[2] = { sw[WRD_WH0LO + wrow + tig], sw[WRD_WH0LO + wrow + tig + 4] };
                    #pragma unroll
                    for (int im = 0; im < 4; im++) {
                        mma_tf32(acc0[im][j], af0[im], bh_);
                        mma_tf32(acc0[im][j], af0[im], bl_);
                    }
                }
                if (do1) {
                    unsigned bx_[2] = { sw[WRD_WX1 + wrow + tig], sw[WRD_WX1 + wrow + tig + 4] };
                    #pragma unroll
                    for (int im = 0; im < 4; im++)
                        mma_tf32(acc1[im][j], af0[im], bx_);
                }
            }

            if (do1) {
                unsigned af1[4][4];
                if (t == 1) {
                    #pragma unroll
                    for (int im = 0; im < 4; im++) {
                        const int r0 = im * 16 + gid;
                        af1[im][0] = f2tf(h1init[(size_t)r0 * H_ + kcol + tig]);
                        af1[im][1] = f2tf(h1init[(size_t)(r0 + 8) * H_ + kcol + tig]);
                        af1[im][2] = f2tf(h1init[(size_t)r0 * H_ + kcol + tig + 4]);
                        af1[im][3] = f2tf(h1init[(size_t)(r0 + 8) * H_ + kcol + tig + 4]);
                    }
                } else {
                    #pragma unroll
                    for (int im = 0; im < 4; im++) {
                        const int r0 = im * 16 + gid;
                        const uint2 p0 = *(const uint2*)&Hp1[(size_t)r0 * H_ + kcol + tig * 2];
                        const uint2 p1 = *(const uint2*)&Hp1[(size_t)(r0 + 8) * H_ + kcol + tig * 2];
                        af1[im][0] = p0.x; af1[im][1] = p1.x;
                        af1[im][2] = p0.y; af1[im][3] = p1.y;
                    }
                }
                #pragma unroll
                for (int j = 0; j < 2; j++) {
                    const int wrow = (wn * 16 + j * 8 + gid) * 132 + klb + kk * 8;
                    unsigned bh_[2] = { sw[WRD_WH1HI + wrow + tig], sw[WRD_WH1HI + wrow + tig + 4] };
                    unsigned bl_[2] = { sw[WRD_WH1LO + wrow + tig], sw[WRD_WH1LO + wrow + tig + 4] };
                    #pragma unroll
                    for (int im = 0; im < 4; im++) {
                        mma_tf32(acc1[im][j], af1[im], bh_);
                        mma_tf32(acc1[im][j], af1[im], bl_);
                    }
                }
            }
        }

        if (wk == 1) {
            #pragma unroll
            for (int im = 0; im < 4; im++) {
                const int r0 = im * 16 + gid;
                #pragma unroll
                for (int j = 0; j < 2; j++) {
                    const int col = wn * 16 + j * 8 + tig * 2;
                    if (do0) {
                        *(float2*)&Pb0[r0 * 72 + col] = make_float2(acc0[im][j][0], acc0[im][j][1]);
                        *(float2*)&Pb0[(r0 + 8) * 72 + col] = make_float2(acc0[im][j][2], acc0[im][j][3]);
                    }
                    if (do1) {
                        *(float2*)&Pb1[r0 * 72 + col] = make_float2(acc1[im][j][0], acc1[im][j][1]);
                        *(float2*)&Pb1[(r0 + 8) * 72 + col] = make_float2(acc1[im][j][2], acc1[im][j][3]);
                    }
                }
            }
        }
        __syncthreads();
        if (wk == 0) {
            #pragma unroll
            for (int im = 0; im < 4; im++) {
                const int r0 = im * 16 + gid;
                #pragma unroll
                for (int j = 0; j < 2; j++) {
                    const int col = wn * 16 + j * 8 + tig * 2;
                    if (do0) {
                        const float2 a0 = *(const float2*)&Pb0[r0 * 72 + col];
                        const float2 a1 = *(const float2*)&Pb0[(r0 + 8) * 72 + col];
                        *(float2*)&Pp0[(size_t)r0 * H_ + n0 + col] =
                            make_float2(acc0[im][j][0] + a0.x, acc0[im][j][1] + a0.y);
                        *(float2*)&Pp0[(size_t)(r0 + 8) * H_ + n0 + col] =
                            make_float2(acc0[im][j][2] + a1.x, acc0[im][j][3] + a1.y);
                    }
                    if (do1) {
                        const float2 a0 = *(const float2*)&Pb1[r0 * 72 + col];
                        const float2 a1 = *(const float2*)&Pb1[(r0 + 8) * 72 + col];
                        *(float2*)&Pp1[(size_t)r0 * H_ + n0 + col] =
                            make_float2(acc1[im][j][0] + a0.x, acc1[im][j][1] + a0.y);
                        *(float2*)&Pp1[(size_t)(r0 + 8) * H_ + n0 + col] =
                            make_float2(acc1[im][j][2] + a1.x, acc1[im][j][3] + a1.y);
                    }
                }
            }
        }

        // Hoist X0 load above the barrier (overlaps barrier wait)
        float xv0 = 0.f, xv1 = 0.f;
        if (do0) {
            const float2 xv = *(const float2*)&X0[(size_t)t * BH + e];
            xv0 = xv.x; xv1 = xv.y;
        }

        gridbar(bid, ++phase);

        const size_t base = (size_t)rm * H_ + rn;
        if (do0) {
            float s0 = xv0, s1 = xv1;
            #pragma unroll
            for (int j = 0; j < 8; j++) {
                const float2 v = __ldcg((const float2*)&g_P[(size_t)j * BH + base]);
                s0 += v.x; s1 += v.y;
            }
            const float h0 = tanhf(s0), h1 = tanhf(s1);
            unsigned* Ht = g_Htf0 + (size_t)t * BH + (size_t)rm * H_;
            Ht[tp0] = f2tf(h0);
            Ht[tp1] = f2tf(h1);
            if (t == T_ - 1) *(float2*)&g_Hfin0[e] = make_float2(h0, h1);
        }
        if (do1) {
            float s0 = b1v0, s1 = b1v1;
            #pragma unroll
            for (int j = 8; j < 16; j++) {
                const float2 v = __ldcg((const float2*)&g_P[(size_t)j * BH + base]);
                s0 += v.x; s1 += v.y;
            }
            const float h0 = tanhf(s0), h1 = tanhf(s1);
            const unsigned u0 = f2tf(h0), u1 = f2tf(h1);
            const int s = t - 1;
            unsigned* Ht = g_Htf1 + (size_t)s * BH + (size_t)rm * H_;
            Ht[tp0] = u0;
            Ht[tp1] = u1;
            *(uint2*)&H1lin[(size_t)s * BH + e] = make_uint2(u0, u1);
            if (s == T_ - 1) *(float2*)&g_Hfin1[e] = make_float2(h0, h1);
        }

        gridbar(bid, ++phase);
    }
}

// ---------------------------------------------------------------------------
// mma.sync TF32 GEMM 128x128, occ 2 — now 4-stage cp.async (wait_group 2):
// two stages always in flight past the consumed one -> 2x latency tolerance.
// ---------------------------------------------------------------------------
#define GS 2560          // words per stage per array (128*20)

__global__ __launch_bounds__(256, 2) void gemm_tf32(
    const unsigned* __restrict__ A, const unsigned* __restrict__ Bm,
    const float* __restrict__ bias, float* __restrict__ C,
    const int* __restrict__ gidx, int N, int K, int ldc)
{
    extern __shared__ unsigned sg[];
    #define AS(st, r, c) sg[(st) * GS + (r) * 20 + (c)]
    #define BS(st, r, c) sg[4 * GS + (st) * GS + (r) * 20 + (c)]

    const int tid  = threadIdx.x;
    const int lane = tid & 31, warp = tid >> 5;
    const int wm = warp >> 1, wn = warp & 1;
    const int gid = lane >> 2, tig = lane & 3;
    const int bm = blockIdx.y * 128, bn = blockIdx.x * 128;

    const int lr = tid >> 2;
    const int lq = (tid & 3) * 4;
    const int ar0 = gidx ? gidx[bm + lr]      : (bm + lr);
    const int ar1 = gidx ? gidx[bm + lr + 64] : (bm + lr + 64);
    const unsigned* Ar0 = A + (size_t)ar0 * K;
    const unsigned* Ar1 = A + (size_t)ar1 * K;
    const int nr0 = min(bn + lr, N - 1);
    const int nr1 = min(bn + lr + 64, N - 1);
    const unsigned* Br0 = Bm + (size_t)nr0 * K;
    const unsigned* Br1 = Bm + (size_t)nr1 * K;

    const unsigned smem_base = (unsigned)__cvta_generic_to_shared(sg);
    const unsigned dA0 = smem_base + (lr * 20 + lq) * 4;
    const unsigned dA1 = smem_base + ((lr + 64) * 20 + lq) * 4;
    const unsigned dB0 = smem_base + (4 * GS + lr * 20 + lq) * 4;
    const unsigned dB1 = smem_base + (4 * GS + (lr + 64) * 20 + lq) * 4;

    const int nst = K >> 4;

    #define ISSUE(st, s)                                                     \
        { const int ko = (s) * 16 + lq; const unsigned so = (st) * GS * 4;   \
          asm volatile("cp.async.cg.shared.global [%0], [%1], 16;\n"         \
                       :: "r"(dA0 + so), "l"(Ar0 + ko));                     \
          asm volatile("cp.async.cg.shared.global [%0], [%1], 16;\n"         \
                       :: "r"(dA1 + so), "l"(Ar1 + ko));                     \
          asm volatile("cp.async.cg.shared.global [%0], [%1], 16;\n"         \
                       :: "r"(dB0 + so), "l"(Br0 + ko));                     \
          asm volatile("cp.async.cg.shared.global [%0], [%1], 16;\n"         \
                       :: "r"(dB1 + so), "l"(Br1 + ko));                     \
          asm volatile("cp.async.commit_group;\n"); }

    ISSUE(0, 0)
    ISSUE(1, 1)
    ISSUE(2, 2)

    float acc[2][8][4];
    #pragma unroll
    for (int i = 0; i < 2; i++)
        #pragma unroll
        for (int j = 0; j < 8; j++)
            #pragma unroll
            for (int q = 0; q < 4; q++) acc[i][j][q] = 0.f;

    for (int s = 0; s < nst; s++) {
        // Exact wait depth: pending groups after stage s completes =
        // min(nst, s+3) - (s+1) = min(2, nst-1-s).
        if (s + 2 < nst)      asm volatile("cp.async.wait_group 2;\n");
        else if (s + 1 < nst) asm volatile("cp.async.wait_group 1;\n");
        else                  asm volatile("cp.async.wait_group 0;\n");
        __syncthreads();

        if (s + 3 < nst) ISSUE((s + 3) & 3, s + 3)

        const int st = s & 3;
        #pragma unroll
        for (int kk = 0; kk < 16; kk += 8) {
            unsigned af[2][4];
            #pragma unroll
            for (int i = 0; i < 2; i++) {
                const int r = wm * 32 + i * 16 + gid;
                af[i][0] = AS(st, r,     kk + tig);
                af[i][1] = AS(st, r + 8, kk + tig);
                af[i][2] = AS(st, r,     kk + tig + 4);
                af[i][3] = AS(st, r + 8, kk + tig + 4);
            }
            #pragma unroll
            for (int jb = 0; jb < 2; jb++) {
                unsigned bf[4][2];
                #pragma unroll
                for (int j2 = 0; j2 < 4; j2++) {
                    const int r = wn * 64 + (jb * 4 + j2) * 8 + gid;
                    bf[j2][0] = BS(st, r, kk + tig);
                    bf[j2][1] = BS(st, r, kk + tig + 4);
                }
                #pragma unroll
                for (int j2 = 0; j2 < 4; j2++) {
                    mma_tf32(acc[0][jb * 4 + j2], af[0], bf[j2]);
                    mma_tf32(acc[1][jb * 4 + j2], af[1], bf[j2]);
                }
            }
        }
    }
    #undef ISSUE
    #undef AS
    #undef BS

    #pragma unroll
    for (int i = 0; i < 2; i++) {
        const int rg = bm + wm * 32 + i * 16 + gid;
        #pragma unroll
        for (int j = 0; j < 8; j++) {
            const int cg = bn + wn * 64 + j * 8 + tig * 2;
            if (cg < N) {
                const float2 bb = *(const float2*)&bias[cg];
                float2 c01 = make_float2(acc[i][j][0] + bb.x, acc[i][j][1] + bb.y);
                float2 c23 = make_float2(acc[i][j][2] + bb.x, acc[i][j][3] + bb.y);
                *(float2*)&C[(size_t)rg * ldc + cg]       = c01;
                *(float2*)&C[(size_t)(rg + 8) * ldc + cg] = c23;
            }
        }
    }
}

// h_final = [h0_fin, h1_fin] -> d_out tail
__global__ void copy_final(const float* __restrict__ F0,
                           const float* __restrict__ F1,
                           float* __restrict__ dst)
{
    const int i = blockIdx.x * blockDim.x + threadIdx.x;
    if (i < BH)          dst[i] = F0[i];
    else if (i < 2 * BH) dst[i] = F1[i - BH];
}

extern "C" void kernel_launch(void* const* d_in, const int* in_sizes, int n_in,
                              void* d_out, int out_size)
{
    (void)in_sizes; (void)n_in; (void)out_size;
    const int*   inputs = (const int*)  d_in[0];
    const float* hidden = (const float*)d_in[1];
    const float* emb    = (const float*)d_in[2];
    const float* Wx0    = (const float*)d_in[3];
    const float* Wx1    = (const float*)d_in[4];
    const float* Wh0    = (const float*)d_in[5];
    const float* bh0    = (const float*)d_in[6];
    const float* Wh1    = (const float*)d_in[7];
    const float* bh1    = (const float*)d_in[8];
    const float* Wy     = (const float*)d_in[9];
    const float* by     = (const float*)d_in[10];
    float* out = (float*)d_out;                    // [T*B*V][L*B*H]

    float *X0, *F0, *F1;
    unsigned *embT, *Wx0T, *WyT, *H1lin;
    cudaGetSymbolAddress((void**)&X0, g_X0);
    cudaGetSymbolAddress((void**)&F0, g_Hfin0);
    cudaGetSymbolAddress((void**)&F1, g_Hfin1);
    cudaGetSymbolAddress((void**)&embT, g_emb_tf);
    cudaGetSymbolAddress((void**)&Wx0T, g_Wx0tf);
    cudaGetSymbolAddress((void**)&WyT,  g_Wytf);
    cudaGetSymbolAddress((void**)&H1lin, g_H1lin);

    const int gemm_smem = 8 * GS * 4;                        // 81920 B (4 stages)
    cudaFuncSetAttribute(gemm_tf32, cudaFuncAttributeMaxDynamicSharedMemorySize, gemm_smem);
    cudaFuncSetAttribute(rnn_fused, cudaFuncAttributeMaxDynamicSharedMemorySize, RNN2_SMEM);

    // Pre-convert GEMM operands to tf32 (emb, Wx0, Wy)
    {
        const int n_emb = V_ * E_ / 4, n_w0 = H_ * E_ / 4, n_wy = V_ * H_ / 4;
        cvt_tf32<<<(n_emb + 255) / 256, 256>>>(emb, embT, n_emb);
        cvt_tf32<<<(n_w0 + 255) / 256, 256>>>(Wx0, Wx0T, n_w0);
        cvt_tf32<<<(n_wy + 255) / 256, 256>>>(Wy, WyT, n_wy);
    }

    // A: X0 = gather(emb_tf) @ Wx0^T + bh0
    gemm_tf32<<<dim3(H_ / 128, MTOT / 128), 256, gemm_smem>>>(
        embT, Wx0T, bh0, X0, inputs, H_, E_, H_);

    // B: fused two-layer recurrence (includes the X1 projection)
    bar_init<<<1, 128>>>();
    rnn_fused<<<128, 256, RNN2_SMEM>>>(
        X0, hidden, hidden + BH, Wh0, Wx1, Wh1, bh1, H1lin);

    // C: logits = h1 @ Wy^T + by
    gemm_tf32<<<dim3((V_ + 127) / 128, MTOT / 128), 256, gemm_smem>>>(
        H1lin, WyT, by, out, nullptr, V_, H_, V_);

    // D: h_final tail
    copy_final<<<(2 * BH + 255) / 256, 256>>>(F0, F1, out + (size_t)MTOT * V_);
}

// round 14
// speedup vs baseline: 1.0221x; 1.0221x over previous
#include <cuda_runtime.h>
#include <math.h>

// Problem constants: T=70, B=64, V=10000, E=512, H=1024, L=2
#define T_  70
#define B_  64
#define V_  10000
#define E_  512
#define H_  1024
#define MTOT (T_ * B_)          // 4480 = 35 * 128
#define BH   (B_ * H_)          // 65536

// Scratch (__device__ globals: allocation-free rule)
__device__ float    g_X0[(size_t)MTOT * H_];
__device__ float    g_P[(size_t)16 * BH];       // partials: [0..8)=y0, [8..16)=y1
__device__ unsigned g_Htf0[(size_t)T_ * BH];    // tf32 h0_t, k-pair interleaved
__device__ unsigned g_Htf1[(size_t)T_ * BH];    // tf32 h1_t, k-pair interleaved (logits A)
__device__ float    g_Hfin0[BH];                // fp32 h0[T-1]
__device__ float    g_Hfin1[BH];                // fp32 h1[T-1]
__device__ unsigned g_flags[128];               // per-block barrier flags

// tf32 pre-converted GEMM operands — k-pair INTERLEAVED layout:
// within each 8-k group, k stored at slot (k&3)*2 + (k>>2).
__device__ unsigned g_emb_tf[(size_t)V_ * E_];
__device__ unsigned g_Wx0tf[(size_t)H_ * E_];
__device__ unsigned g_Wytf [(size_t)V_ * H_];

__global__ void bar_init() { g_flags[threadIdx.x] = 0u; }

__device__ __forceinline__ unsigned f2tf(float x) {
    unsigned r; asm("cvt.rna.tf32.f32 %0, %1;" : "=r"(r) : "f"(x)); return r;
}

// fp32 -> tf32(rna), k-pair interleaved within each 8-element group.
// float4 i covers elements i*4..i*4+3; group g = (i*4) & ~7; slot base
// s0 = 0 if (i*4)%8==0 else 1; element j -> slot s0 + 2j.
__global__ void cvt_tf32i(const float* __restrict__ s, unsigned* __restrict__ d, int n4) {
    const int i = blockIdx.x * 256 + threadIdx.x;
    if (i < n4) {
        const float4 v = ((const float4*)s)[i];
        const int base = (i * 4) & ~7;
        const int s0   = (i * 4) & 4 ? 1 : 0;
        unsigned* o = d + base + s0;
        o[0] = f2tf(v.x); o[2] = f2tf(v.y);
        o[4] = f2tf(v.z); o[6] = f2tf(v.w);
    }
}

// Contention-free grid barrier (128 co-resident blocks, 1/SM).
__device__ __forceinline__ void gridbar(int bid, unsigned phase) {
    __threadfence();
    __syncthreads();
    if (threadIdx.x == 0)
        atomicExch(&g_flags[bid], phase);
    if (threadIdx.x < 128) {
        volatile unsigned* vf = g_flags;
        while (vf[threadIdx.x] < phase) __nanosleep(32);
    }
    __syncthreads();
    __threadfence();
}

__device__ __forceinline__ void mma_tf32(float c[4], const unsigned a[4], const unsigned b[2]) {
    asm volatile(
        "mma.sync.aligned.m16n8k8.row.col.f32.tf32.tf32.f32 "
        "{%0,%1,%2,%3}, {%4,%5,%6,%7}, {%8,%9}, {%0,%1,%2,%3};\n"
        : "+f"(c[0]), "+f"(c[1]), "+f"(c[2]), "+f"(c[3])
        : "r"(a[0]), "r"(a[1]), "r"(a[2]), "r"(a[3]), "r"(b[0]), "r"(b[1]));
}

// ---------------------------------------------------------------------------
// FUSED two-layer persistent recurrence — R12 WIN version; only change:
// H1lin store removed (logits now reads g_Htf1 directly).
// ---------------------------------------------------------------------------
#define WRD_WH0HI 0
#define WRD_WH0LO 8448
#define WRD_WH1HI 16896
#define WRD_WH1LO 25344
#define WRD_WX1   33792
#define WRD_PB0   42240
#define WRD_PB1   46848
#define RNN2_SMEM (51456 * 4)          // 205824 B

__global__ __launch_bounds__(256) void rnn_fused(
    const float* __restrict__ X0,
    const float* __restrict__ h0init, const float* __restrict__ h1init,
    const float* __restrict__ Wh0, const float* __restrict__ Wx1,
    const float* __restrict__ Wh1, const float* __restrict__ bh1)
{
    extern __shared__ unsigned sw[];
    float* Pb0 = (float*)(sw + WRD_PB0);   // [64][72]
    float* Pb1 = (float*)(sw + WRD_PB1);   // [64][72]

    const int tid = threadIdx.x;
    const int bid = blockIdx.x;
    const int ntile = bid >> 3;
    const int ks    = bid & 7;
    const int n0    = ntile * 64;
    const int kb    = ks * 128;

    // Load W slices once (resident all intervals)
    {
        const int r  = tid >> 2;
        const int q4 = (tid & 3) * 4;
        #pragma unroll
        for (int s = 0; s < 8; s++) {
            const int c  = q4 + s * 16;
            const size_t gi = (size_t)(n0 + r) * H_ + kb + c;
            const int wo = r * 132 + c;
            {
                const float4 w = *(const float4*)&Wh0[gi];
                unsigned a0 = f2tf(w.x), a1 = f2tf(w.y), a2 = f2tf(w.z), a3 = f2tf(w.w);
                unsigned* ph = &sw[WRD_WH0HI + wo];
                unsigned* pl = &sw[WRD_WH0LO + wo];
                ph[0] = a0; ph[1] = a1; ph[2] = a2; ph[3] = a3;
                pl[0] = f2tf(w.x - __uint_as_float(a0));
                pl[1] = f2tf(w.y - __uint_as_float(a1));
                pl[2] = f2tf(w.z - __uint_as_float(a2));
                pl[3] = f2tf(w.w - __uint_as_float(a3));
            }
            {
                const float4 w = *(const float4*)&Wh1[gi];
                unsigned a0 = f2tf(w.x), a1 = f2tf(w.y), a2 = f2tf(w.z), a3 = f2tf(w.w);
                unsigned* ph = &sw[WRD_WH1HI + wo];
                unsigned* pl = &sw[WRD_WH1LO + wo];
                ph[0] = a0; ph[1] = a1; ph[2] = a2; ph[3] = a3;
                pl[0] = f2tf(w.x - __uint_as_float(a0));
                pl[1] = f2tf(w.y - __uint_as_float(a1));
                pl[2] = f2tf(w.z - __uint_as_float(a2));
                pl[3] = f2tf(w.w - __uint_as_float(a3));
            }
            {
                const float4 w = *(const float4*)&Wx1[gi];
                unsigned* p = &sw[WRD_WX1 + wo];
                p[0] = f2tf(w.x); p[1] = f2tf(w.y);
                p[2] = f2tf(w.z); p[3] = f2tf(w.w);
            }
        }
    }
    __syncthreads();

    const int wid  = tid >> 5, lane = tid & 31;
    const int wk   = wid & 1;           // k-half (64 k)
    const int wn   = wid >> 1;          // 0..3 (16-n strip)
    const int gid  = lane >> 2, tig = lane & 3;
    const int kwb  = kb + wk * 64;
    const int klb  = wk * 64;

    float* Pp0 = g_P + (size_t)ks * BH;
    float* Pp1 = g_P + (size_t)(8 + ks) * BH;

    const int e  = bid * 512 + tid * 2;
    const int rm = e >> 10;
    const int rn = e & 1023;
    const int b8 = rn & ~7;
    const int o0 = rn & 7;
    const int tp0 = b8 + ((o0 & 3) * 2) + (o0 >> 2);
    const int tp1 = b8 + (((o0 + 1) & 3) * 2) + ((o0 + 1) >> 2);
    const float b1v0 = bh1[rn], b1v1 = bh1[rn + 1];

    unsigned phase = 0;

    #pragma unroll 1
    for (int t = 0; t <= T_; t++) {
        const bool do0 = (t < T_);
        const bool do1 = (t >= 1);

        float acc0[4][2][4], acc1[4][2][4];
        #pragma unroll
        for (int im = 0; im < 4; im++)
            #pragma unroll
            for (int j = 0; j < 2; j++)
                #pragma unroll
                for (int q = 0; q < 4; q++) { acc0[im][j][q] = 0.f; acc1[im][j][q] = 0.f; }

        const unsigned* Hp0 = g_Htf0 + (size_t)(t - 1) * BH;
        const unsigned* Hp1 = g_Htf1 + (size_t)(t - 2) * BH;

        #pragma unroll 2
        for (int kk = 0; kk < 8; kk++) {
            const int kcol = kwb + kk * 8;

            unsigned af0[4][4];
            if (t == 0) {
                #pragma unroll
                for (int im = 0; im < 4; im++) {
                    const int r0 = im * 16 + gid;
                    af0[im][0] = f2tf(h0init[(size_t)r0 * H_ + kcol + tig]);
                    af0[im][1] = f2tf(h0init[(size_t)(r0 + 8) * H_ + kcol + tig]);
                    af0[im][2] = f2tf(h0init[(size_t)r0 * H_ + kcol + tig + 4]);
                    af0[im][3] = f2tf(h0init[(size_t)(r0 + 8) * H_ + kcol + tig + 4]);
                }
            } else {
                #pragma unroll
                for (int im = 0; im < 4; im++) {
                    const int r0 = im * 16 + gid;
                    const uint2 p0 = *(const uint2*)&Hp0[(size_t)r0 * H_ + kcol + tig * 2];
                    const uint2 p1 = *(const uint2*)&Hp0[(size_t)(r0 + 8) * H_ + kcol + tig * 2];
                    af0[im][0] = p0.x; af0[im][1] = p1.x;
                    af0[im][2] = p0.y; af0[im][3] = p1.y;
                }
            }
            #pragma unroll
            for (int j = 0; j < 2; j++) {
                const int wrow = (wn * 16 + j * 8 + gid) * 132 + klb + kk * 8;
                if (do0) {
                    unsigned bh_[2] = { sw[WRD_WH0HI + wrow + tig], sw[WRD_WH0HI + wrow + tig + 4] };
                    unsigned bl_[2] = { sw[WRD_WH0LO + wrow + tig], sw[WRD_WH0LO + wrow + tig + 4] };
                    #pragma unroll
                    for (int im = 0; im < 4; im++) {
                        mma_tf32(acc0[im][j], af0[im], bh_);
                        mma_tf32(acc0[im][j], af0[im], bl_);
                    }
                }
                if (do1) {
                    unsigned bx_[2] = { sw[WRD_WX1 + wrow + tig], sw[WRD_WX1 + wrow + tig + 4] };
                    #pragma unroll
                    for (int im = 0; im < 4; im++)
                        mma_tf32(acc1[im][j], af0[im], bx_);
                }
            }

            if (do1) {
                unsigned af1[4][4];
                if (t == 1) {
                    #pragma unroll
                    for (int im = 0; im < 4; im++) {
                        const int r0 = im * 16 + gid;
                        af1[im][0] = f2tf(h1init[(size_t)r0 * H_ + kcol + tig]);
                        af1[im][1] = f2tf(h1init[(size_t)(r0 + 8) * H_ + kcol + tig]);
                        af1[im][2] = f2tf(h1init[(size_t)r0 * H_ + kcol + tig + 4]);
                        af1[im][3] = f2tf(h1init[(size_t)(r0 + 8) * H_ + kcol + tig + 4]);
                    }
                } else {
                    #pragma unroll
                    for (int im = 0; im < 4; im++) {
                        const int r0 = im * 16 + gid;
                        const uint2 p0 = *(const uint2*)&Hp1[(size_t)r0 * H_ + kcol + tig * 2];
                        const uint2 p1 = *(const uint2*)&Hp1[(size_t)(r0 + 8) * H_ + kcol + tig * 2];
                        af1[im][0] = p0.x; af1[im][1] = p1.x;
                        af1[im][2] = p0.y; af1[im][3] = p1.y;
                    }
                }
                #pragma unroll
                for (int j = 0; j < 2; j++) {
                    const int wrow = (wn * 16 + j * 8 + gid) * 132 + klb + kk * 8;
                    unsigned bh_[2] = { sw[WRD_WH1HI + wrow + tig], sw[WRD_WH1HI + wrow + tig + 4] };
                    unsigned bl_[2] = { sw[WRD_WH1LO + wrow + tig], sw[WRD_WH1LO + wrow + tig + 4] };
                    #pragma unroll
                    for (int im = 0; im < 4; im++) {
                        mma_tf32(acc1[im][j], af1[im], bh_);
                        mma_tf32(acc1[im][j], af1[im], bl_);
                    }
                }
            }
        }

        if (wk == 1) {
            #pragma unroll
            for (int im = 0; im < 4; im++) {
                const int r0 = im * 16 + gid;
                #pragma unroll
                for (int j = 0; j < 2; j++) {
                    const int col = wn * 16 + j * 8 + tig * 2;
                    if (do0) {
                        *(float2*)&Pb0[r0 * 72 + col] = make_float2(acc0[im][j][0], acc0[im][j][1]);
                        *(float2*)&Pb0[(r0 + 8) * 72 + col] = make_float2(acc0[im][j][2], acc0[im][j][3]);
                    }
                    if (do1) {
                        *(float2*)&Pb1[r0 * 72 + col] = make_float2(acc1[im][j][0], acc1[im][j][1]);
                        *(float2*)&Pb1[(r0 + 8) * 72 + col] = make_float2(acc1[im][j][2], acc1[im][j][3]);
                    }
                }
            }
        }
        __syncthreads();
        if (wk == 0) {
            #pragma unroll
            for (int im = 0; im < 4; im++) {
                const int r0 = im * 16 + gid;
                #pragma unroll
                for (int j = 0; j < 2; j++) {
                    const int col = wn * 16 + j * 8 + tig * 2;
                    if (do0) {
                        const float2 a0 = *(const float2*)&Pb0[r0 * 72 + col];
                        const float2 a1 = *(const float2*)&Pb0[(r0 + 8) * 72 + col];
                        *(float2*)&Pp0[(size_t)r0 * H_ + n0 + col] =
                            make_float2(acc0[im][j][0] + a0.x, acc0[im][j][1] + a0.y);
                        *(float2*)&Pp0[(size_t)(r0 + 8) * H_ + n0 + col] =
                            make_float2(acc0[im][j][2] + a1.x, acc0[im][j][3] + a1.y);
                    }
                    if (do1) {
                        const float2 a0 = *(const float2*)&Pb1[r0 * 72 + col];
                        const float2 a1 = *(const float2*)&Pb1[(r0 + 8) * 72 + col];
                        *(float2*)&Pp1[(size_t)r0 * H_ + n0 + col] =
                            make_float2(acc1[im][j][0] + a0.x, acc1[im][j][1] + a0.y);
                        *(float2*)&Pp1[(size_t)(r0 + 8) * H_ + n0 + col] =
                            make_float2(acc1[im][j][2] + a1.x, acc1[im][j][3] + a1.y);
                    }
                }
            }
        }

        // Hoist X0 load above the barrier (overlaps barrier wait)
        float xv0 = 0.f, xv1 = 0.f;
        if (do0) {
            const float2 xv = *(const float2*)&X0[(size_t)t * BH + e];
            xv0 = xv.x; xv1 = xv.y;
        }

        gridbar(bid, ++phase);

        const size_t base = (size_t)rm * H_ + rn;
        if (do0) {
            float s0 = xv0, s1 = xv1;
            #pragma unroll
            for (int j = 0; j < 8; j++) {
                const float2 v = __ldcg((const float2*)&g_P[(size_t)j * BH + base]);
                s0 += v.x; s1 += v.y;
            }
            const float h0 = tanhf(s0), h1 = tanhf(s1);
            unsigned* Ht = g_Htf0 + (size_t)t * BH + (size_t)rm * H_;
            Ht[tp0] = f2tf(h0);
            Ht[tp1] = f2tf(h1);
            if (t == T_ - 1) *(float2*)&g_Hfin0[e] = make_float2(h0, h1);
        }
        if (do1) {
            float s0 = b1v0, s1 = b1v1;
            #pragma unroll
            for (int j = 8; j < 16; j++) {
                const float2 v = __ldcg((const float2*)&g_P[(size_t)j * BH + base]);
                s0 += v.x; s1 += v.y;
            }
            const float h0 = tanhf(s0), h1 = tanhf(s1);
            const int s = t - 1;
            unsigned* Ht = g_Htf1 + (size_t)s * BH + (size_t)rm * H_;
            Ht[tp0] = f2tf(h0);
            Ht[tp1] = f2tf(h1);
            if (s == T_ - 1) *(float2*)&g_Hfin1[e] = make_float2(h0, h1);
        }

        gridbar(bid, ++phase);
    }
}

// ---------------------------------------------------------------------------
// mma.sync TF32 GEMM 128x128, occ 2, 3-stage cp.async.
// Operands in k-pair-interleaved global layout -> each lane's (tig, tig+4)
// fragment pair is one LDS.64. Row stride 24 words: uint2 loads provably
// bank-conflict-free (gid 0..3 cover all 32 banks disjointly).
// ---------------------------------------------------------------------------
#define GS 3072          // words per stage per array (128*24)

__global__ __launch_bounds__(256, 2) void gemm_tf32(
    const unsigned* __restrict__ A, const unsigned* __restrict__ Bm,
    const float* __restrict__ bias, float* __restrict__ C,
    const int* __restrict__ gidx, int N, int K, int ldc)
{
    extern __shared__ unsigned sg[];
    #define ASW(st, r, c) sg[(st) * GS + (r) * 24 + (c)]
    #define BSW(st, r, c) sg[3 * GS + (st) * GS + (r) * 24 + (c)]

    const int tid  = threadIdx.x;
    const int lane = tid & 31, warp = tid >> 5;
    const int wm = warp >> 1, wn = warp & 1;
    const int gid = lane >> 2, tig = lane & 3;
    const int bm = blockIdx.y * 128, bn = blockIdx.x * 128;

    const int lr = tid >> 2;
    const int lq = (tid & 3) * 4;
    const int ar0 = gidx ? gidx[bm + lr]      : (bm + lr);
    const int ar1 = gidx ? gidx[bm + lr + 64] : (bm + lr + 64);
    const unsigned* Ar0 = A + (size_t)ar0 * K;
    const unsigned* Ar1 = A + (size_t)ar1 * K;
    const int nr0 = min(bn + lr, N - 1);
    const int nr1 = min(bn + lr + 64, N - 1);
    const unsigned* Br0 = Bm + (size_t)nr0 * K;
    const unsigned* Br1 = Bm + (size_t)nr1 * K;

    const unsigned smem_base = (unsigned)__cvta_generic_to_shared(sg);
    const unsigned dA0 = smem_base + (lr * 24 + lq) * 4;
    const unsigned dA1 = smem_base + ((lr + 64) * 24 + lq) * 4;
    const unsigned dB0 = smem_base + (3 * GS + lr * 24 + lq) * 4;
    const unsigned dB1 = smem_base + (3 * GS + (lr + 64) * 24 + lq) * 4;

    const int nst = K >> 4;

    #define ISSUE(st, s)                                                     \
        { const int ko = (s) * 16 + lq; const unsigned so = (st) * GS * 4;   \
          asm volatile("cp.async.cg.shared.global [%0], [%1], 16;\n"         \
                       :: "r"(dA0 + so), "l"(Ar0 + ko));                     \
          asm volatile("cp.async.cg.shared.global [%0], [%1], 16;\n"         \
                       :: "r"(dA1 + so), "l"(Ar1 + ko));                     \
          asm volatile("cp.async.cg.shared.global [%0], [%1], 16;\n"         \
                       :: "r"(dB0 + so), "l"(Br0 + ko));                     \
          asm volatile("cp.async.cg.shared.global [%0], [%1], 16;\n"         \
                       :: "r"(dB1 + so), "l"(Br1 + ko));                     \
          asm volatile("cp.async.commit_group;\n"); }

    ISSUE(0, 0)
    ISSUE(1, 1)

    float acc[2][8][4];
    #pragma unroll
    for (int i = 0; i < 2; i++)
        #pragma unroll
        for (int j = 0; j < 8; j++)
            #pragma unroll
            for (int q = 0; q < 4; q++) acc[i][j][q] = 0.f;

    for (int s = 0; s < nst; s++) {
        if (s == nst - 1) asm volatile("cp.async.wait_group 0;\n");
        else              asm volatile("cp.async.wait_group 1;\n");
        __syncthreads();

        if (s + 2 < nst) ISSUE((s + 2) % 3, s + 2)

        const int st = s % 3;
        #pragma unroll
        for (int kk = 0; kk < 16; kk += 8) {
            unsigned af[2][4];
            #pragma unroll
            for (int i = 0; i < 2; i++) {
                const int r = wm * 32 + i * 16 + gid;
                const uint2 p0 = *(const uint2*)&ASW(st, r,     kk + tig * 2);
                const uint2 p1 = *(const uint2*)&ASW(st, r + 8, kk + tig * 2);
                af[i][0] = p0.x; af[i][1] = p1.x;
                af[i][2] = p0.y; af[i][3] = p1.y;
            }
            #pragma unroll
            for (int jb = 0; jb < 2; jb++) {
                unsigned bf[4][2];
                #pragma unroll
                for (int j2 = 0; j2 < 4; j2++) {
                    const int r = wn * 64 + (jb * 4 + j2) * 8 + gid;
                    const uint2 pb = *(const uint2*)&BSW(st, r, kk + tig * 2);
                    bf[j2][0] = pb.x; bf[j2][1] = pb.y;
                }
                #pragma unroll
                for (int j2 = 0; j2 < 4; j2++) {
                    mma_tf32(acc[0][jb * 4 + j2], af[0], bf[j2]);
                    mma_tf32(acc[1][jb * 4 + j2], af[1], bf[j2]);
                }
            }
        }
    }
    #undef ISSUE
    #undef ASW
    #undef BSW

    #pragma unroll
    for (int i = 0; i < 2; i++) {
        const int rg = bm + wm * 32 + i * 16 + gid;
        #pragma unroll
        for (int j = 0; j < 8; j++) {
            const int cg = bn + wn * 64 + j * 8 + tig * 2;
            if (cg < N) {
                const float2 bb = *(const float2*)&bias[cg];
                float2 c01 = make_float2(acc[i][j][0] + bb.x, acc[i][j][1] + bb.y);
                float2 c23 = make_float2(acc[i][j][2] + bb.x, acc[i][j][3] + bb.y);
                *(float2*)&C[(size_t)rg * ldc + cg]       = c01;
                *(float2*)&C[(size_t)(rg + 8) * ldc + cg] = c23;
            }
        }
    }
}

// h_final = [h0_fin, h1_fin] -> d_out tail
__global__ void copy_final(const float* __restrict__ F0,
                           const float* __restrict__ F1,
                           float* __restrict__ dst)
{
    const int i = blockIdx.x * blockDim.x + threadIdx.x;
    if (i < BH)          dst[i] = F0[i];
    else if (i < 2 * BH) dst[i] = F1[i - BH];
}

extern "C" void kernel_launch(void* const* d_in, const int* in_sizes, int n_in,
                              void* d_out, int out_size)
{
    (void)in_sizes; (void)n_in; (void)out_size;
    const int*   inputs = (const int*)  d_in[0];
    const float* hidden = (const float*)d_in[1];
    const float* emb    = (const float*)d_in[2];
    const float* Wx0    = (const float*)d_in[3];
    const float* Wx1    = (const float*)d_in[4];
    const float* Wh0    = (const float*)d_in[5];
    const float* bh0    = (const float*)d_in[6];
    const float* Wh1    = (const float*)d_in[7];
    const float* bh1    = (const float*)d_in[8];
    const float* Wy     = (const float*)d_in[9];
    const float* by     = (const float*)d_in[10];
    float* out = (float*)d_out;                    // [T*B*V][L*B*H]

    float *X0, *F0, *F1;
    unsigned *embT, *Wx0T, *WyT, *Htf1;
    cudaGetSymbolAddress((void**)&X0, g_X0);
    cudaGetSymbolAddress((void**)&F0, g_Hfin0);
    cudaGetSymbolAddress((void**)&F1, g_Hfin1);
    cudaGetSymbolAddress((void**)&embT, g_emb_tf);
    cudaGetSymbolAddress((void**)&Wx0T, g_Wx0tf);
    cudaGetSymbolAddress((void**)&WyT,  g_Wytf);
    cudaGetSymbolAddress((void**)&Htf1, g_Htf1);

    const int gemm_smem = 6 * GS * 4;                        // 73728 B (3 stages, stride 24)
    cudaFuncSetAttribute(gemm_tf32, cudaFuncAttributeMaxDynamicSharedMemorySize, gemm_smem);
    cudaFuncSetAttribute(rnn_fused, cudaFuncAttributeMaxDynamicSharedMemorySize, RNN2_SMEM);

    // Pre-convert GEMM operands to tf32, k-pair interleaved
    {
        const int n_emb = V_ * E_ / 4, n_w0 = H_ * E_ / 4, n_wy = V_ * H_ / 4;
        cvt_tf32i<<<(n_emb + 255) / 256, 256>>>(emb, embT, n_emb);
        cvt_tf32i<<<(n_w0 + 255) / 256, 256>>>(Wx0, Wx0T, n_w0);
        cvt_tf32i<<<(n_wy + 255) / 256, 256>>>(Wy, WyT, n_wy);
    }

    // A: X0 = gather(emb_tf) @ Wx0^T + bh0
    gemm_tf32<<<dim3(H_ / 128, MTOT / 128), 256, gemm_smem>>>(
        embT, Wx0T, bh0, X0, inputs, H_, E_, H_);

    // B: fused two-layer recurrence (includes the X1 projection)
    bar_init<<<1, 128>>>();
    rnn_fused<<<128, 256, RNN2_SMEM>>>(
        X0, hidden, hidden + BH, Wh0, Wx1, Wh1, bh1);

    // C: logits = h1 @ Wy^T + by  (A = g_Htf1, already interleaved tf32)
    gemm_tf32<<<dim3((V_ + 127) / 128, MTOT / 128), 256, gemm_smem>>>(
        Htf1, WyT, by, out, nullptr, V_, H_, V_);

    // D: h_final tail
    copy_final<<<(2 * BH + 255) / 256, 256>>>(F0, F1, out + (size_t)MTOT * V_);
}